// round 10
// baseline (speedup 1.0000x reference)
#include <cuda_runtime.h>
#include <cuda_bf16.h>
#include <cuda_fp16.h>
#include <cstdint>

// Problem constants
#define BSZ   32
#define SSZ   1024
#define DSZ   768
#define HSZ   128
#define RSZ   48
#define APP   (SSZ + 1)        // 1025
#define NTOK  (BSZ * SSZ)      // 32768
#define MHEAD (BSZ * APP)      // 32800

// Scratch (device globals)
__device__ __half g_headH[(size_t)MHEAD * HSZ];           // fp16 head
__device__ __half g_tailH[(size_t)NTOK * HSZ];            // fp16 tail
__device__ __half g_W16[(size_t)2 * HSZ * DSZ];           // W^T [branch][n][k] fp16
// Fragment-ordered fp16 B image per r: uint4 units: r*2048 + ks*256 + g*32 + lane
__device__ uint4 g_Bfrag[(size_t)RSZ * 2048];

// ---------------------------------------------------------------------------
// PTX helpers (target-suffix-free)
// ---------------------------------------------------------------------------
__device__ __forceinline__ uint32_t smem_u32(const void* p) {
    uint32_t a;
    asm("{ .reg .u64 t; cvta.to.shared.u64 t, %1; cvt.u32.u64 %0, t; }" : "=r"(a) : "l"(p));
    return a;
}

#define CP16(dst, src) \
    asm volatile("cp.async.cg.shared.global [%0], [%1], 16;" :: "r"(dst), "l"(src) : "memory")
#define CP_COMMIT() asm volatile("cp.async.commit_group;" ::: "memory")
#define CP_WAIT0()  asm volatile("cp.async.wait_group 0;" ::: "memory")
#define CP_WAIT1()  asm volatile("cp.async.wait_group 1;" ::: "memory")

#define LDMX4(r, addr) \
    asm volatile("ldmatrix.sync.aligned.m8n8.x4.shared.b16 {%0,%1,%2,%3}, [%4];" \
        : "=r"((r)[0]), "=r"((r)[1]), "=r"((r)[2]), "=r"((r)[3]) : "r"(addr))

// fp16 MMA
#define MMA_FP(c, a, b0, b1) \
    asm volatile("mma.sync.aligned.m16n8k16.row.col.f32.f16.f16.f32 " \
        "{%0,%1,%2,%3}, {%4,%5,%6,%7}, {%8,%9}, {%0,%1,%2,%3};" \
        : "+f"((c)[0]), "+f"((c)[1]), "+f"((c)[2]), "+f"((c)[3]) \
        : "r"((a)[0]), "r"((a)[1]), "r"((a)[2]), "r"((a)[3]), "r"(b0), "r"(b1))

__device__ __forceinline__ uint32_t pack_fp16(__half a, __half b) {
    return (uint32_t)__half_as_ushort(a) | ((uint32_t)__half_as_ushort(b) << 16);
}

// ---------------------------------------------------------------------------
// Kernel 0a: prep K -> fragment-ordered fp16 B images.
//   uint32 index v in [0, 8192): v = ks*1024 + g*128 + lane*4 + hw2
//     pair = hw2>>1, reg = hw2&1
//     n = (2g+pair)*8 + (lane>>2); h0 = ks*16 + reg*8 + (lane&3)*2
// ---------------------------------------------------------------------------
__global__ __launch_bounds__(256) void prep_k(const float* __restrict__ Kmat)
{
    extern __shared__ float ksm[];           // [128][129]
    const int r   = blockIdx.x;
    const int tid = threadIdx.x;
#pragma unroll
    for (int j = 0; j < 64; j++) {
        int idx = tid + j * 256;
        int h = idx >> 7, n = idx & 127;
        ksm[h * 129 + n] = Kmat[(size_t)h * (HSZ * RSZ) + r * HSZ + n];
    }
    __syncthreads();

    uint32_t* outH = (uint32_t*)(g_Bfrag + (size_t)r * 2048);
#pragma unroll
    for (int j = 0; j < 32; j++) {
        int v = tid + j * 256;               // 0..8191
        int ks   = v >> 10;
        int rem  = v & 1023;
        int g    = rem >> 7;
        int rem2 = rem & 127;
        int lane = rem2 >> 2;
        int hw2  = rem2 & 3;
        int pair = hw2 >> 1, reg = hw2 & 1;
        int n  = (2 * g + pair) * 8 + (lane >> 2);
        int h0 = ks * 16 + reg * 8 + (lane & 3) * 2;
        float f0 = ksm[h0 * 129 + n];
        float f1 = ksm[(h0 + 1) * 129 + n];
        outH[v] = pack_fp16(__float2half_rn(f0), __float2half_rn(f1));
    }
}

// ---------------------------------------------------------------------------
// Kernel 0b: prep W — transpose Wh/Wt -> fp16 W^T [n][k].
// ---------------------------------------------------------------------------
__global__ __launch_bounds__(256) void prep_w(const float* __restrict__ Wh,
                                              const float* __restrict__ Wt)
{
    __shared__ float tw[32 * 129];
    const int kb = blockIdx.x;
    const int br = blockIdx.y;
    const float* W = br ? Wt : Wh;
    const int tid = threadIdx.x;
#pragma unroll
    for (int j = 0; j < 16; j++) {
        int idx = tid + j * 256;
        int k = idx >> 7;
        int n = idx & 127;
        tw[k * 129 + n] = W[(size_t)(kb * 32 + k) * HSZ + n];
    }
    __syncthreads();
#pragma unroll
    for (int j = 0; j < 16; j++) {
        int idx = tid + j * 256;
        int n = idx >> 5;
        int k = idx & 31;
        g_W16[(size_t)br * HSZ * DSZ + (size_t)n * DSZ + kb * 32 + k] =
            __float2half_rn(tw[k * 129 + n]);
    }
}

// ---------------------------------------------------------------------------
// Kernel 1: dual FF GEMM, fp16 1-pass: fp16(x) @ fp16(W^T), fp32 accum.
//   CTA = 128 rows x 128 cols, K=768 in 24 chunks of 32, 2-stage B pipeline.
//   Branch 0 emits fp16 head; branch 1 emits fp16 tail.
// ---------------------------------------------------------------------------
#define FFROW 80
#define FF_AT (128 * FFROW)                        // 10240
#define FF_BB FF_AT
#define FF_BS FF_AT                                // 10240 per stage
#define FF_SMEM (FF_BB + 2 * FF_BS)                // 30720

__global__ __launch_bounds__(256) void ff_mma(
    const float* __restrict__ x,
    const float* __restrict__ root,
    const float* __restrict__ bh, const float* __restrict__ bt)
{
    extern __shared__ char sm[];
    const uint32_t sb = smem_u32(sm);

    const int branch = blockIdx.y;
    const int M      = (branch == 0) ? MHEAD : NTOK;
    const int m0     = blockIdx.x * 128;
    if (m0 >= M) return;

    const float* bias = (branch == 0) ? bh : bt;
    const __half* WB  = g_W16 + (size_t)branch * HSZ * DSZ;

    const int tid  = threadIdx.x;
    const int lane = tid & 31;
    const int warp = tid >> 5;
    const int wm   = warp >> 2;
    const int wn   = warp & 3;

    const float* arow[4];
    bool rowok[4];
    int rown[4], colf[4];
#pragma unroll
    for (int i = 0; i < 4; i++) {
        int c   = tid + i * 256;
        int row = c >> 3;
        int c4  = c & 7;
        rown[i] = row; colf[i] = c4;
        int g = m0 + row;
        const float* p = nullptr;
        bool ok = (g < M);
        if (ok) {
            if (branch == 0) {
                int b  = g / APP;
                int ii = g - b * APP;
                p = (ii == 0) ? root : (x + (size_t)(b * SSZ + (ii - 1)) * DSZ);
            } else {
                p = x + (size_t)g * DSZ;
            }
        }
        arow[i] = p; rowok[i] = ok;
    }

    auto load_B = [&](uint32_t buf, int k0) {
#pragma unroll
        for (int i = 0; i < 2; i++) {
            int c   = tid + i * 256;
            int row = c >> 2;
            int c4  = c & 3;
            CP16(buf + row * FFROW + c4 * 16, WB + (size_t)row * DSZ + k0 + c4 * 8);
        }
    };

    float4 va[4];
#pragma unroll
    for (int i = 0; i < 4; i++)
        va[i] = rowok[i] ? *(const float4*)(arow[i] + colf[i] * 4)
                         : make_float4(0.f, 0.f, 0.f, 0.f);
    load_B(sb + FF_BB, 0);
    CP_COMMIT();

    float acc[4][4][4];
#pragma unroll
    for (int mt = 0; mt < 4; mt++)
#pragma unroll
        for (int nt = 0; nt < 4; nt++)
#pragma unroll
            for (int e = 0; e < 4; e++) acc[mt][nt][e] = 0.f;

    const uint32_t aLaneOff = (uint32_t)(wm * 64 + (lane & 15)) * FFROW
                            + (uint32_t)(lane >> 4) * 16;
    const uint32_t bLaneOff = (uint32_t)(wn * 32 + (lane & 7) + ((lane >> 4) << 3)) * FFROW
                            + (uint32_t)((lane >> 3) & 1) * 16;

#pragma unroll 1
    for (int ch = 0; ch < 24; ch++) {
        const int nxt = ch + 1;
        if (nxt < 24) load_B(sb + FF_BB + (nxt & 1) * FF_BS, nxt * 32);
        CP_COMMIT();

#pragma unroll
        for (int i = 0; i < 4; i++) {
            uint32_t w0 = pack_fp16(__float2half_rn(va[i].x), __float2half_rn(va[i].y));
            uint32_t w1 = pack_fp16(__float2half_rn(va[i].z), __float2half_rn(va[i].w));
            *(uint2*)(sm + rown[i] * FFROW + colf[i] * 8) = make_uint2(w0, w1);
        }
        if (nxt < 24) {
#pragma unroll
            for (int i = 0; i < 4; i++)
                va[i] = rowok[i] ? *(const float4*)(arow[i] + nxt * 32 + colf[i] * 4)
                                 : make_float4(0.f, 0.f, 0.f, 0.f);
        }
        CP_WAIT1();
        __syncthreads();

        const uint32_t aB = sb + aLaneOff;
        const uint32_t bB = sb + FF_BB + (ch & 1) * FF_BS + bLaneOff;
#pragma unroll
        for (int ks = 0; ks < 2; ks++) {
            uint32_t aF[4][4];
#pragma unroll
            for (int mt = 0; mt < 4; mt++)
                LDMX4(aF[mt], aB + (uint32_t)mt * 16 * FFROW + (uint32_t)ks * 32);
            uint32_t bF[2][4];
#pragma unroll
            for (int np = 0; np < 2; np++)
                LDMX4(bF[np], bB + (uint32_t)np * 16 * FFROW + (uint32_t)ks * 32);
#pragma unroll
            for (int mt = 0; mt < 4; mt++)
#pragma unroll
                for (int nt = 0; nt < 4; nt++)
                    MMA_FP(acc[mt][nt], aF[mt],
                           bF[nt >> 1][(nt & 1) * 2], bF[nt >> 1][(nt & 1) * 2 + 1]);
        }
        __syncthreads();
    }

    float2 bv[4];
#pragma unroll
    for (int nt = 0; nt < 4; nt++)
        bv[nt] = *(const float2*)&bias[wn * 32 + nt * 8 + (lane & 3) * 2];

#pragma unroll
    for (int mt = 0; mt < 4; mt++) {
#pragma unroll
        for (int half = 0; half < 2; half++) {
            const int row  = wm * 64 + mt * 16 + (lane >> 2) + half * 8;
            const int grow = m0 + row;
            if (grow >= M) continue;
#pragma unroll
            for (int nt = 0; nt < 4; nt++) {
                const int col = wn * 32 + nt * 8 + (lane & 3) * 2;
                float f0 = fmaxf(acc[mt][nt][half * 2 + 0] + bv[nt].x, 0.f);
                float f1 = fmaxf(acc[mt][nt][half * 2 + 1] + bv[nt].y, 0.f);
                uint32_t pk = pack_fp16(__float2half_rn(f0), __float2half_rn(f1));
                if (branch == 0)
                    *(uint32_t*)&g_headH[(size_t)grow * HSZ + col] = pk;
                else
                    *(uint32_t*)&g_tailH[(size_t)grow * HSZ + col] = pk;
            }
        }
    }
}

// ---------------------------------------------------------------------------
// Kernel 2: biaffine v7 — fp16 1-pass, warp tile m64 x n64.
//   CTA = 256 tokens x 24 r, 256 threads, 8 warps = 4 m-groups x 2 n-groups.
//   A (head fp16) + tail (fp16) resident in smem. Each warp reads its n64
//   half of B fragments via LDG.128; 4 LDSM + 4 LDG feed 32 MMAs per ks.
//   Epilogue: warp-local quad reduce, 2-warp smem combine (1 barrier per r,
//   double-buffered).
// ---------------------------------------------------------------------------
#define AROW 272
#define ATILE (256 * AROW)             // 69632
#define TTILE (256 * AROW)
#define BI_RED (ATILE + TTILE)         // 139264
#define BI_SMEM (BI_RED + 2048)        // 141312

__global__ __launch_bounds__(256) void biaffine_mma(
    const int* __restrict__ head_id,
    float* __restrict__ out)
{
    extern __shared__ char sm[];
    const uint32_t sb = smem_u32(sm);
    float* red = (float*)(sm + BI_RED);

    const int t0  = blockIdx.x * 256;
    const int r0  = blockIdx.y * 24;
    const int tid = threadIdx.x;
    const int lane = tid & 31;
    const int warp = tid >> 5;
    const int wm   = warp >> 1;        // 0..3 (64 tokens each)
    const int wn   = warp & 1;         // 0..1 (64 k-cols each)

    // Stage A (gathered head rows) and tail, both fp16, via cp.async.
#pragma unroll
    for (int i = 0; i < 16; i++) {
        int c   = tid + i * 256;       // 0..4095
        int row = c >> 4;
        int col = c & 15;
        int t   = t0 + row;
        int hid = head_id[t];
        size_t hbase = ((size_t)(t >> 10) * APP + hid) * HSZ + col * 8;
        CP16(sb + (uint32_t)row * AROW + col * 16, g_headH + hbase);
        CP16(sb + ATILE + (uint32_t)row * AROW + col * 16,
             g_tailH + (size_t)t * HSZ + col * 8);
    }
    CP_COMMIT();
    CP_WAIT0();
    __syncthreads();

    const uint32_t aBase = sb + (uint32_t)(wm * 64 + (lane & 15)) * AROW
                         + (uint32_t)(lane >> 4) * 16;

    // tail smem read base: row = wm*64 + mt*16 + (lane>>2) + half*8
    const char* tbase = sm + ATILE
                      + ((uint32_t)(wm * 64 + (lane >> 2)) * AROW)
                      + (uint32_t)(wn * 64 + (lane & 3) * 2) * 2;

#pragma unroll 1
    for (int rr = 0; rr < 24; rr++) {
        const int r = r0 + rr;
        const uint4* __restrict__ bF = g_Bfrag + (size_t)r * 2048 + wn * 128 + lane;

        float acc[4][8][4];
#pragma unroll
        for (int mt = 0; mt < 4; mt++)
#pragma unroll
            for (int nb = 0; nb < 8; nb++)
#pragma unroll
                for (int e = 0; e < 4; e++) acc[mt][nb][e] = 0.f;

#pragma unroll
        for (int ks = 0; ks < 8; ks++) {
            uint32_t a[4][4];
#pragma unroll
            for (int mt = 0; mt < 4; mt++)
                LDMX4(a[mt], aBase + (uint32_t)mt * 16 * AROW + ks * 32);
            const uint4* bk = bF + ks * 256;
#pragma unroll
            for (int gl = 0; gl < 4; gl++) {
                uint4 bv = bk[gl * 32];
#pragma unroll
                for (int mt = 0; mt < 4; mt++) {
                    MMA_FP(acc[mt][2 * gl],     a[mt], bv.x, bv.y);
                    MMA_FP(acc[mt][2 * gl + 1], a[mt], bv.z, bv.w);
                }
            }
        }

        // partial k-dot with tail (this warp's 64 cols), quad reduce
        float p[4][2];
#pragma unroll
        for (int mt = 0; mt < 4; mt++) {
#pragma unroll
            for (int half = 0; half < 2; half++) {
                const char* trow = tbase + (uint32_t)(mt * 16 + half * 8) * AROW;
                float s = 0.f;
#pragma unroll
                for (int nb = 0; nb < 8; nb++) {
                    uint32_t tv = *(const uint32_t*)(trow + nb * 16);
                    float2 tf = __half22float2(*(const __half2*)&tv);
                    s += acc[mt][nb][half * 2 + 0] * tf.x
                       + acc[mt][nb][half * 2 + 1] * tf.y;
                }
                s += __shfl_xor_sync(0xffffffffu, s, 1);
                s += __shfl_xor_sync(0xffffffffu, s, 2);
                p[mt][half] = s;
            }
        }

        float* rbuf = red + (rr & 1) * 256;
        if (wn == 0 && (lane & 3) == 0) {
#pragma unroll
            for (int mt = 0; mt < 4; mt++)
#pragma unroll
                for (int half = 0; half < 2; half++) {
                    int lrow = wm * 64 + mt * 16 + (lane >> 2) + half * 8;
                    rbuf[lrow] = p[mt][half];
                }
        }
        __syncthreads();
        if (wn == 1 && (lane & 3) == 0) {
#pragma unroll
            for (int mt = 0; mt < 4; mt++)
#pragma unroll
                for (int half = 0; half < 2; half++) {
                    int lrow = wm * 64 + mt * 16 + (lane >> 2) + half * 8;
                    out[(size_t)(t0 + lrow) * RSZ + r] = rbuf[lrow] + p[mt][half];
                }
        }
    }
}

// ---------------------------------------------------------------------------
extern "C" void kernel_launch(void* const* d_in, const int* in_sizes, int n_in,
                              void* d_out, int out_size)
{
    const float* x       = (const float*)d_in[0];
    const int*   head_id = (const int*)  d_in[1];
    const float* root    = (const float*)d_in[2];
    const float* Wh      = (const float*)d_in[3];
    const float* bh      = (const float*)d_in[4];
    const float* Wt      = (const float*)d_in[5];
    const float* bt      = (const float*)d_in[6];
    const float* Kmat    = (const float*)d_in[7];
    float*       out     = (float*)d_out;

    const int prep_smem = 128 * 129 * sizeof(float);   // 66048
    cudaFuncSetAttribute(prep_k, cudaFuncAttributeMaxDynamicSharedMemorySize, prep_smem);
    prep_k<<<RSZ, 256, prep_smem>>>(Kmat);
    prep_w<<<dim3(24, 2), 256>>>(Wh, Wt);

    cudaFuncSetAttribute(ff_mma, cudaFuncAttributeMaxDynamicSharedMemorySize, FF_SMEM);
    ff_mma<<<dim3(257, 2), 256, FF_SMEM>>>(x, root, bh, bt);

    cudaFuncSetAttribute(biaffine_mma, cudaFuncAttributeMaxDynamicSharedMemorySize, BI_SMEM);
    biaffine_mma<<<dim3(NTOK / 256, 2), 256, BI_SMEM>>>(head_id, out);
}

// round 11
// speedup vs baseline: 1.2553x; 1.2553x over previous
#include <cuda_runtime.h>
#include <cuda_bf16.h>
#include <cuda_fp16.h>
#include <cstdint>

// Problem constants
#define BSZ   32
#define SSZ   1024
#define DSZ   768
#define HSZ   128
#define RSZ   48
#define APP   (SSZ + 1)        // 1025
#define NTOK  (BSZ * SSZ)      // 32768
#define MHEAD (BSZ * APP)      // 32800

// Scratch (device globals)
__device__ __half g_headH[(size_t)MHEAD * HSZ];           // fp16 head
__device__ __half g_tailH[(size_t)NTOK * HSZ];            // fp16 tail
__device__ __half g_W16[(size_t)2 * HSZ * DSZ];           // W^T [branch][n][k] fp16
// Fragment-ordered fp16 B image per r: uint4 units: r*2048 + ks*256 + g*32 + lane
__device__ uint4 g_Bfrag[(size_t)RSZ * 2048];

// ---------------------------------------------------------------------------
// PTX helpers (target-suffix-free)
// ---------------------------------------------------------------------------
__device__ __forceinline__ uint32_t smem_u32(const void* p) {
    uint32_t a;
    asm("{ .reg .u64 t; cvta.to.shared.u64 t, %1; cvt.u32.u64 %0, t; }" : "=r"(a) : "l"(p));
    return a;
}

#define CP16(dst, src) \
    asm volatile("cp.async.cg.shared.global [%0], [%1], 16;" :: "r"(dst), "l"(src) : "memory")
#define CP_COMMIT() asm volatile("cp.async.commit_group;" ::: "memory")
#define CP_WAIT0()  asm volatile("cp.async.wait_group 0;" ::: "memory")
#define CP_WAIT1()  asm volatile("cp.async.wait_group 1;" ::: "memory")

#define LDMX4(r, addr) \
    asm volatile("ldmatrix.sync.aligned.m8n8.x4.shared.b16 {%0,%1,%2,%3}, [%4];" \
        : "=r"((r)[0]), "=r"((r)[1]), "=r"((r)[2]), "=r"((r)[3]) : "r"(addr))

// fp16 MMA
#define MMA_FP(c, a, b0, b1) \
    asm volatile("mma.sync.aligned.m16n8k16.row.col.f32.f16.f16.f32 " \
        "{%0,%1,%2,%3}, {%4,%5,%6,%7}, {%8,%9}, {%0,%1,%2,%3};" \
        : "+f"((c)[0]), "+f"((c)[1]), "+f"((c)[2]), "+f"((c)[3]) \
        : "r"((a)[0]), "r"((a)[1]), "r"((a)[2]), "r"((a)[3]), "r"(b0), "r"(b1))

__device__ __forceinline__ uint32_t pack_fp16(__half a, __half b) {
    return (uint32_t)__half_as_ushort(a) | ((uint32_t)__half_as_ushort(b) << 16);
}

// ---------------------------------------------------------------------------
// Kernel 0a: prep K -> fragment-ordered fp16 B images.
// ---------------------------------------------------------------------------
__global__ __launch_bounds__(256) void prep_k(const float* __restrict__ Kmat)
{
    extern __shared__ float ksm[];           // [128][129]
    const int r   = blockIdx.x;
    const int tid = threadIdx.x;
#pragma unroll
    for (int j = 0; j < 64; j++) {
        int idx = tid + j * 256;
        int h = idx >> 7, n = idx & 127;
        ksm[h * 129 + n] = Kmat[(size_t)h * (HSZ * RSZ) + r * HSZ + n];
    }
    __syncthreads();

    uint32_t* outH = (uint32_t*)(g_Bfrag + (size_t)r * 2048);
#pragma unroll
    for (int j = 0; j < 32; j++) {
        int v = tid + j * 256;               // 0..8191
        int ks   = v >> 10;
        int rem  = v & 1023;
        int g    = rem >> 7;
        int rem2 = rem & 127;
        int lane = rem2 >> 2;
        int hw2  = rem2 & 3;
        int pair = hw2 >> 1, reg = hw2 & 1;
        int n  = (2 * g + pair) * 8 + (lane >> 2);
        int h0 = ks * 16 + reg * 8 + (lane & 3) * 2;
        float f0 = ksm[h0 * 129 + n];
        float f1 = ksm[(h0 + 1) * 129 + n];
        outH[v] = pack_fp16(__float2half_rn(f0), __float2half_rn(f1));
    }
}

// ---------------------------------------------------------------------------
// Kernel 0b: prep W — transpose Wh/Wt -> fp16 W^T [n][k].
// ---------------------------------------------------------------------------
__global__ __launch_bounds__(256) void prep_w(const float* __restrict__ Wh,
                                              const float* __restrict__ Wt)
{
    __shared__ float tw[32 * 129];
    const int kb = blockIdx.x;
    const int br = blockIdx.y;
    const float* W = br ? Wt : Wh;
    const int tid = threadIdx.x;
#pragma unroll
    for (int j = 0; j < 16; j++) {
        int idx = tid + j * 256;
        int k = idx >> 7;
        int n = idx & 127;
        tw[k * 129 + n] = W[(size_t)(kb * 32 + k) * HSZ + n];
    }
    __syncthreads();
#pragma unroll
    for (int j = 0; j < 16; j++) {
        int idx = tid + j * 256;
        int n = idx >> 5;
        int k = idx & 31;
        g_W16[(size_t)br * HSZ * DSZ + (size_t)n * DSZ + kb * 32 + k] =
            __float2half_rn(tw[k * 129 + n]);
    }
}

// ---------------------------------------------------------------------------
// Kernel 1: dual FF GEMM, fp16 1-pass (proven in R10).
// ---------------------------------------------------------------------------
#define FFROW 80
#define FF_AT (128 * FFROW)                        // 10240
#define FF_BB FF_AT
#define FF_BS FF_AT
#define FF_SMEM (FF_BB + 2 * FF_BS)                // 30720

__global__ __launch_bounds__(256) void ff_mma(
    const float* __restrict__ x,
    const float* __restrict__ root,
    const float* __restrict__ bh, const float* __restrict__ bt)
{
    extern __shared__ char sm[];
    const uint32_t sb = smem_u32(sm);

    const int branch = blockIdx.y;
    const int M      = (branch == 0) ? MHEAD : NTOK;
    const int m0     = blockIdx.x * 128;
    if (m0 >= M) return;

    const float* bias = (branch == 0) ? bh : bt;
    const __half* WB  = g_W16 + (size_t)branch * HSZ * DSZ;

    const int tid  = threadIdx.x;
    const int lane = tid & 31;
    const int warp = tid >> 5;
    const int wm   = warp >> 2;
    const int wn   = warp & 3;

    const float* arow[4];
    bool rowok[4];
    int rown[4], colf[4];
#pragma unroll
    for (int i = 0; i < 4; i++) {
        int c   = tid + i * 256;
        int row = c >> 3;
        int c4  = c & 7;
        rown[i] = row; colf[i] = c4;
        int g = m0 + row;
        const float* p = nullptr;
        bool ok = (g < M);
        if (ok) {
            if (branch == 0) {
                int b  = g / APP;
                int ii = g - b * APP;
                p = (ii == 0) ? root : (x + (size_t)(b * SSZ + (ii - 1)) * DSZ);
            } else {
                p = x + (size_t)g * DSZ;
            }
        }
        arow[i] = p; rowok[i] = ok;
    }

    auto load_B = [&](uint32_t buf, int k0) {
#pragma unroll
        for (int i = 0; i < 2; i++) {
            int c   = tid + i * 256;
            int row = c >> 2;
            int c4  = c & 3;
            CP16(buf + row * FFROW + c4 * 16, WB + (size_t)row * DSZ + k0 + c4 * 8);
        }
    };

    float4 va[4];
#pragma unroll
    for (int i = 0; i < 4; i++)
        va[i] = rowok[i] ? *(const float4*)(arow[i] + colf[i] * 4)
                         : make_float4(0.f, 0.f, 0.f, 0.f);
    load_B(sb + FF_BB, 0);
    CP_COMMIT();

    float acc[4][4][4];
#pragma unroll
    for (int mt = 0; mt < 4; mt++)
#pragma unroll
        for (int nt = 0; nt < 4; nt++)
#pragma unroll
            for (int e = 0; e < 4; e++) acc[mt][nt][e] = 0.f;

    const uint32_t aLaneOff = (uint32_t)(wm * 64 + (lane & 15)) * FFROW
                            + (uint32_t)(lane >> 4) * 16;
    const uint32_t bLaneOff = (uint32_t)(wn * 32 + (lane & 7) + ((lane >> 4) << 3)) * FFROW
                            + (uint32_t)((lane >> 3) & 1) * 16;

#pragma unroll 1
    for (int ch = 0; ch < 24; ch++) {
        const int nxt = ch + 1;
        if (nxt < 24) load_B(sb + FF_BB + (nxt & 1) * FF_BS, nxt * 32);
        CP_COMMIT();

#pragma unroll
        for (int i = 0; i < 4; i++) {
            uint32_t w0 = pack_fp16(__float2half_rn(va[i].x), __float2half_rn(va[i].y));
            uint32_t w1 = pack_fp16(__float2half_rn(va[i].z), __float2half_rn(va[i].w));
            *(uint2*)(sm + rown[i] * FFROW + colf[i] * 8) = make_uint2(w0, w1);
        }
        if (nxt < 24) {
#pragma unroll
            for (int i = 0; i < 4; i++)
                va[i] = rowok[i] ? *(const float4*)(arow[i] + nxt * 32 + colf[i] * 4)
                                 : make_float4(0.f, 0.f, 0.f, 0.f);
        }
        CP_WAIT1();
        __syncthreads();

        const uint32_t aB = sb + aLaneOff;
        const uint32_t bB = sb + FF_BB + (ch & 1) * FF_BS + bLaneOff;
#pragma unroll
        for (int ks = 0; ks < 2; ks++) {
            uint32_t aF[4][4];
#pragma unroll
            for (int mt = 0; mt < 4; mt++)
                LDMX4(aF[mt], aB + (uint32_t)mt * 16 * FFROW + (uint32_t)ks * 32);
            uint32_t bF[2][4];
#pragma unroll
            for (int np = 0; np < 2; np++)
                LDMX4(bF[np], bB + (uint32_t)np * 16 * FFROW + (uint32_t)ks * 32);
#pragma unroll
            for (int mt = 0; mt < 4; mt++)
#pragma unroll
                for (int nt = 0; nt < 4; nt++)
                    MMA_FP(acc[mt][nt], aF[mt],
                           bF[nt >> 1][(nt & 1) * 2], bF[nt >> 1][(nt & 1) * 2 + 1]);
        }
        __syncthreads();
    }

    float2 bv[4];
#pragma unroll
    for (int nt = 0; nt < 4; nt++)
        bv[nt] = *(const float2*)&bias[wn * 32 + nt * 8 + (lane & 3) * 2];

#pragma unroll
    for (int mt = 0; mt < 4; mt++) {
#pragma unroll
        for (int half = 0; half < 2; half++) {
            const int row  = wm * 64 + mt * 16 + (lane >> 2) + half * 8;
            const int grow = m0 + row;
            if (grow >= M) continue;
#pragma unroll
            for (int nt = 0; nt < 4; nt++) {
                const int col = wn * 32 + nt * 8 + (lane & 3) * 2;
                float f0 = fmaxf(acc[mt][nt][half * 2 + 0] + bv[nt].x, 0.f);
                float f1 = fmaxf(acc[mt][nt][half * 2 + 1] + bv[nt].y, 0.f);
                uint32_t pk = pack_fp16(__float2half_rn(f0), __float2half_rn(f1));
                if (branch == 0)
                    *(uint32_t*)&g_headH[(size_t)grow * HSZ + col] = pk;
                else
                    *(uint32_t*)&g_tailH[(size_t)grow * HSZ + col] = pk;
            }
        }
    }
}

// ---------------------------------------------------------------------------
// Kernel 2: biaffine v8 — R9's m32 x n64 tile (proven 2 CTA/SM) with the
// per-r barrier removed: partial k-dots go to per-r smem slots (redA/redB),
// ONE __syncthreads at the end, then a combined coalesced store pass.
//   CTA = 128 tokens x 24 r, 256 threads, 8 warps = 4 wm x 2 wn.
// ---------------------------------------------------------------------------
#define AROW 272
#define ATILE (128 * AROW)             // 34816
#define TTILE (128 * AROW)
#define BI_REDA (ATILE + TTILE)        // 69632
#define BI_REDB (BI_REDA + 24 * 128 * 4)   // +12288
#define BI_SMEM (BI_REDB + 24 * 128 * 4)   // 94208

__global__ __launch_bounds__(256, 2) void biaffine_mma(
    const int* __restrict__ head_id,
    float* __restrict__ out)
{
    extern __shared__ char sm[];
    const uint32_t sb = smem_u32(sm);
    float* redA = (float*)(sm + BI_REDA);
    float* redB = (float*)(sm + BI_REDB);

    const int t0  = blockIdx.x * 128;
    const int r0  = blockIdx.y * 24;
    const int tid = threadIdx.x;
    const int lane = tid & 31;
    const int warp = tid >> 5;
    const int wm   = warp >> 1;        // 0..3 (32 tokens each)
    const int wn   = warp & 1;         // 0..1 (64 k-cols each)

    // Stage A (gathered head rows) and tail, both fp16, via cp.async.
#pragma unroll
    for (int i = 0; i < 8; i++) {
        int c   = tid + i * 256;
        int row = c >> 4;
        int col = c & 15;
        int t   = t0 + row;
        int hid = head_id[t];
        size_t hbase = ((size_t)(t >> 10) * APP + hid) * HSZ + col * 8;
        CP16(sb + (uint32_t)row * AROW + col * 16, g_headH + hbase);
        CP16(sb + ATILE + (uint32_t)row * AROW + col * 16,
             g_tailH + (size_t)t * HSZ + col * 8);
    }
    CP_COMMIT();
    CP_WAIT0();
    __syncthreads();

    const uint32_t aBase = sb + (uint32_t)(wm * 32 + (lane & 15)) * AROW
                         + (uint32_t)(lane >> 4) * 16;

    // tail smem read base: row = wm*32 + mt*16 + (lane>>2) + half*8
    const char* tbase = sm + ATILE
                      + ((uint32_t)(wm * 32 + (lane >> 2)) * AROW)
                      + (uint32_t)(wn * 64 + (lane & 3) * 2) * 2;

    float* rbuf = (wn == 0) ? redA : redB;

#pragma unroll 1
    for (int rr = 0; rr < 24; rr++) {
        const int r = r0 + rr;
        const uint4* __restrict__ bF = g_Bfrag + (size_t)r * 2048 + wn * 128 + lane;

        float acc[2][8][4];
#pragma unroll
        for (int mt = 0; mt < 2; mt++)
#pragma unroll
            for (int nb = 0; nb < 8; nb++)
#pragma unroll
                for (int e = 0; e < 4; e++) acc[mt][nb][e] = 0.f;

#pragma unroll
        for (int ks = 0; ks < 8; ks++) {
            uint32_t a0[4], a1[4];
            LDMX4(a0, aBase + ks * 32);
            LDMX4(a1, aBase + 16 * AROW + ks * 32);
            const uint4* bk = bF + ks * 256;
#pragma unroll
            for (int gl = 0; gl < 4; gl++) {
                uint4 bv = bk[gl * 32];
                MMA_FP(acc[0][2 * gl],     a0, bv.x, bv.y);
                MMA_FP(acc[0][2 * gl + 1], a0, bv.z, bv.w);
                MMA_FP(acc[1][2 * gl],     a1, bv.x, bv.y);
                MMA_FP(acc[1][2 * gl + 1], a1, bv.z, bv.w);
            }
        }

        // partial k-dot with tail (this warp's 64 cols), quad reduce,
        // store to this r's slot (no barrier).
#pragma unroll
        for (int mt = 0; mt < 2; mt++) {
#pragma unroll
            for (int half = 0; half < 2; half++) {
                const char* trow = tbase + (uint32_t)(mt * 16 + half * 8) * AROW;
                float s = 0.f;
#pragma unroll
                for (int nb = 0; nb < 8; nb++) {
                    uint32_t tv = *(const uint32_t*)(trow + nb * 16);
                    float2 tf = __half22float2(*(const __half2*)&tv);
                    s += acc[mt][nb][half * 2 + 0] * tf.x
                       + acc[mt][nb][half * 2 + 1] * tf.y;
                }
                s += __shfl_xor_sync(0xffffffffu, s, 1);
                s += __shfl_xor_sync(0xffffffffu, s, 2);
                if ((lane & 3) == 0) {
                    int lrow = wm * 32 + mt * 16 + (lane >> 2) + half * 8;
                    rbuf[rr * 128 + lrow] = s;
                }
            }
        }
    }

    // single barrier, then combined coalesced store pass
    __syncthreads();
#pragma unroll
    for (int i = 0; i < 12; i++) {
        int idx  = tid + i * 256;          // 0..3071
        int lrow = idx / 24;
        int rr   = idx - lrow * 24;
        out[(size_t)(t0 + lrow) * RSZ + (r0 + rr)] =
            redA[rr * 128 + lrow] + redB[rr * 128 + lrow];
    }
}

// ---------------------------------------------------------------------------
extern "C" void kernel_launch(void* const* d_in, const int* in_sizes, int n_in,
                              void* d_out, int out_size)
{
    const float* x       = (const float*)d_in[0];
    const int*   head_id = (const int*)  d_in[1];
    const float* root    = (const float*)d_in[2];
    const float* Wh      = (const float*)d_in[3];
    const float* bh      = (const float*)d_in[4];
    const float* Wt      = (const float*)d_in[5];
    const float* bt      = (const float*)d_in[6];
    const float* Kmat    = (const float*)d_in[7];
    float*       out     = (float*)d_out;

    const int prep_smem = 128 * 129 * sizeof(float);   // 66048
    cudaFuncSetAttribute(prep_k, cudaFuncAttributeMaxDynamicSharedMemorySize, prep_smem);
    prep_k<<<RSZ, 256, prep_smem>>>(Kmat);
    prep_w<<<dim3(24, 2), 256>>>(Wh, Wt);

    cudaFuncSetAttribute(ff_mma, cudaFuncAttributeMaxDynamicSharedMemorySize, FF_SMEM);
    ff_mma<<<dim3(257, 2), 256, FF_SMEM>>>(x, root, bh, bt);

    cudaFuncSetAttribute(biaffine_mma, cudaFuncAttributeMaxDynamicSharedMemorySize, BI_SMEM);
    biaffine_mma<<<dim3(NTOK / 128, 2), 256, BI_SMEM>>>(head_id, out);
}

// round 12
// speedup vs baseline: 1.3688x; 1.0904x over previous
#include <cuda_runtime.h>
#include <cuda_bf16.h>
#include <cuda_fp16.h>
#include <cstdint>

// Problem constants
#define BSZ   32
#define SSZ   1024
#define DSZ   768
#define HSZ   128
#define RSZ   48
#define APP   (SSZ + 1)        // 1025
#define NTOK  (BSZ * SSZ)      // 32768
#define MHEAD (BSZ * APP)      // 32800

// Scratch (device globals)
__device__ __half g_headH[(size_t)MHEAD * HSZ];           // fp16 head
__device__ __half g_tailH[(size_t)NTOK * HSZ];            // fp16 tail
__device__ __half g_W16[(size_t)2 * HSZ * DSZ];           // W^T [branch][n][k] fp16
// Fragment-ordered fp16 B image per r: uint4 units: r*2048 + ks*256 + g*32 + lane
__device__ uint4 g_Bfrag[(size_t)RSZ * 2048];

// ---------------------------------------------------------------------------
// PTX helpers (target-suffix-free)
// ---------------------------------------------------------------------------
__device__ __forceinline__ uint32_t smem_u32(const void* p) {
    uint32_t a;
    asm("{ .reg .u64 t; cvta.to.shared.u64 t, %1; cvt.u32.u64 %0, t; }" : "=r"(a) : "l"(p));
    return a;
}

#define CP16(dst, src) \
    asm volatile("cp.async.cg.shared.global [%0], [%1], 16;" :: "r"(dst), "l"(src) : "memory")
#define CP_COMMIT() asm volatile("cp.async.commit_group;" ::: "memory")
#define CP_WAIT0()  asm volatile("cp.async.wait_group 0;" ::: "memory")
#define CP_WAIT1()  asm volatile("cp.async.wait_group 1;" ::: "memory")

#define LDMX4(r, addr) \
    asm volatile("ldmatrix.sync.aligned.m8n8.x4.shared.b16 {%0,%1,%2,%3}, [%4];" \
        : "=r"((r)[0]), "=r"((r)[1]), "=r"((r)[2]), "=r"((r)[3]) : "r"(addr))

// fp16 MMA
#define MMA_FP(c, a, b0, b1) \
    asm volatile("mma.sync.aligned.m16n8k16.row.col.f32.f16.f16.f32 " \
        "{%0,%1,%2,%3}, {%4,%5,%6,%7}, {%8,%9}, {%0,%1,%2,%3};" \
        : "+f"((c)[0]), "+f"((c)[1]), "+f"((c)[2]), "+f"((c)[3]) \
        : "r"((a)[0]), "r"((a)[1]), "r"((a)[2]), "r"((a)[3]), "r"(b0), "r"(b1))

__device__ __forceinline__ uint32_t pack_fp16(__half a, __half b) {
    return (uint32_t)__half_as_ushort(a) | ((uint32_t)__half_as_ushort(b) << 16);
}

// ---------------------------------------------------------------------------
// Kernel 0a: prep K -> fragment-ordered fp16 B images.
// ---------------------------------------------------------------------------
__global__ __launch_bounds__(256) void prep_k(const float* __restrict__ Kmat)
{
    extern __shared__ float ksm[];           // [128][129]
    const int r   = blockIdx.x;
    const int tid = threadIdx.x;
#pragma unroll
    for (int j = 0; j < 64; j++) {
        int idx = tid + j * 256;
        int h = idx >> 7, n = idx & 127;
        ksm[h * 129 + n] = Kmat[(size_t)h * (HSZ * RSZ) + r * HSZ + n];
    }
    __syncthreads();

    uint32_t* outH = (uint32_t*)(g_Bfrag + (size_t)r * 2048);
#pragma unroll
    for (int j = 0; j < 32; j++) {
        int v = tid + j * 256;               // 0..8191
        int ks   = v >> 10;
        int rem  = v & 1023;
        int g    = rem >> 7;
        int rem2 = rem & 127;
        int lane = rem2 >> 2;
        int hw2  = rem2 & 3;
        int pair = hw2 >> 1, reg = hw2 & 1;
        int n  = (2 * g + pair) * 8 + (lane >> 2);
        int h0 = ks * 16 + reg * 8 + (lane & 3) * 2;
        float f0 = ksm[h0 * 129 + n];
        float f1 = ksm[(h0 + 1) * 129 + n];
        outH[v] = pack_fp16(__float2half_rn(f0), __float2half_rn(f1));
    }
}

// ---------------------------------------------------------------------------
// Kernel 0b: prep W — transpose Wh/Wt -> fp16 W^T [n][k].
// ---------------------------------------------------------------------------
__global__ __launch_bounds__(256) void prep_w(const float* __restrict__ Wh,
                                              const float* __restrict__ Wt)
{
    __shared__ float tw[32 * 129];
    const int kb = blockIdx.x;
    const int br = blockIdx.y;
    const float* W = br ? Wt : Wh;
    const int tid = threadIdx.x;
#pragma unroll
    for (int j = 0; j < 16; j++) {
        int idx = tid + j * 256;
        int k = idx >> 7;
        int n = idx & 127;
        tw[k * 129 + n] = W[(size_t)(kb * 32 + k) * HSZ + n];
    }
    __syncthreads();
#pragma unroll
    for (int j = 0; j < 16; j++) {
        int idx = tid + j * 256;
        int n = idx >> 5;
        int k = idx & 31;
        g_W16[(size_t)br * HSZ * DSZ + (size_t)n * DSZ + kb * 32 + k] =
            __float2half_rn(tw[k * 129 + n]);
    }
}

// ---------------------------------------------------------------------------
// Kernel 1: dual FF GEMM, fp16 1-pass (proven in R10/R11).
// ---------------------------------------------------------------------------
#define FFROW 80
#define FF_AT (128 * FFROW)                        // 10240
#define FF_BB FF_AT
#define FF_BS FF_AT
#define FF_SMEM (FF_BB + 2 * FF_BS)                // 30720

__global__ __launch_bounds__(256) void ff_mma(
    const float* __restrict__ x,
    const float* __restrict__ root,
    const float* __restrict__ bh, const float* __restrict__ bt)
{
    extern __shared__ char sm[];
    const uint32_t sb = smem_u32(sm);

    const int branch = blockIdx.y;
    const int M      = (branch == 0) ? MHEAD : NTOK;
    const int m0     = blockIdx.x * 128;
    if (m0 >= M) return;

    const float* bias = (branch == 0) ? bh : bt;
    const __half* WB  = g_W16 + (size_t)branch * HSZ * DSZ;

    const int tid  = threadIdx.x;
    const int lane = tid & 31;
    const int warp = tid >> 5;
    const int wm   = warp >> 2;
    const int wn   = warp & 3;

    const float* arow[4];
    bool rowok[4];
    int rown[4], colf[4];
#pragma unroll
    for (int i = 0; i < 4; i++) {
        int c   = tid + i * 256;
        int row = c >> 3;
        int c4  = c & 7;
        rown[i] = row; colf[i] = c4;
        int g = m0 + row;
        const float* p = nullptr;
        bool ok = (g < M);
        if (ok) {
            if (branch == 0) {
                int b  = g / APP;
                int ii = g - b * APP;
                p = (ii == 0) ? root : (x + (size_t)(b * SSZ + (ii - 1)) * DSZ);
            } else {
                p = x + (size_t)g * DSZ;
            }
        }
        arow[i] = p; rowok[i] = ok;
    }

    auto load_B = [&](uint32_t buf, int k0) {
#pragma unroll
        for (int i = 0; i < 2; i++) {
            int c   = tid + i * 256;
            int row = c >> 2;
            int c4  = c & 3;
            CP16(buf + row * FFROW + c4 * 16, WB + (size_t)row * DSZ + k0 + c4 * 8);
        }
    };

    float4 va[4];
#pragma unroll
    for (int i = 0; i < 4; i++)
        va[i] = rowok[i] ? *(const float4*)(arow[i] + colf[i] * 4)
                         : make_float4(0.f, 0.f, 0.f, 0.f);
    load_B(sb + FF_BB, 0);
    CP_COMMIT();

    float acc[4][4][4];
#pragma unroll
    for (int mt = 0; mt < 4; mt++)
#pragma unroll
        for (int nt = 0; nt < 4; nt++)
#pragma unroll
            for (int e = 0; e < 4; e++) acc[mt][nt][e] = 0.f;

    const uint32_t aLaneOff = (uint32_t)(wm * 64 + (lane & 15)) * FFROW
                            + (uint32_t)(lane >> 4) * 16;
    const uint32_t bLaneOff = (uint32_t)(wn * 32 + (lane & 7) + ((lane >> 4) << 3)) * FFROW
                            + (uint32_t)((lane >> 3) & 1) * 16;

#pragma unroll 1
    for (int ch = 0; ch < 24; ch++) {
        const int nxt = ch + 1;
        if (nxt < 24) load_B(sb + FF_BB + (nxt & 1) * FF_BS, nxt * 32);
        CP_COMMIT();

#pragma unroll
        for (int i = 0; i < 4; i++) {
            uint32_t w0 = pack_fp16(__float2half_rn(va[i].x), __float2half_rn(va[i].y));
            uint32_t w1 = pack_fp16(__float2half_rn(va[i].z), __float2half_rn(va[i].w));
            *(uint2*)(sm + rown[i] * FFROW + colf[i] * 8) = make_uint2(w0, w1);
        }
        if (nxt < 24) {
#pragma unroll
            for (int i = 0; i < 4; i++)
                va[i] = rowok[i] ? *(const float4*)(arow[i] + nxt * 32 + colf[i] * 4)
                                 : make_float4(0.f, 0.f, 0.f, 0.f);
        }
        CP_WAIT1();
        __syncthreads();

        const uint32_t aB = sb + aLaneOff;
        const uint32_t bB = sb + FF_BB + (ch & 1) * FF_BS + bLaneOff;
#pragma unroll
        for (int ks = 0; ks < 2; ks++) {
            uint32_t aF[4][4];
#pragma unroll
            for (int mt = 0; mt < 4; mt++)
                LDMX4(aF[mt], aB + (uint32_t)mt * 16 * FFROW + (uint32_t)ks * 32);
            uint32_t bF[2][4];
#pragma unroll
            for (int np = 0; np < 2; np++)
                LDMX4(bF[np], bB + (uint32_t)np * 16 * FFROW + (uint32_t)ks * 32);
#pragma unroll
            for (int mt = 0; mt < 4; mt++)
#pragma unroll
                for (int nt = 0; nt < 4; nt++)
                    MMA_FP(acc[mt][nt], aF[mt],
                           bF[nt >> 1][(nt & 1) * 2], bF[nt >> 1][(nt & 1) * 2 + 1]);
        }
        __syncthreads();
    }

    float2 bv[4];
#pragma unroll
    for (int nt = 0; nt < 4; nt++)
        bv[nt] = *(const float2*)&bias[wn * 32 + nt * 8 + (lane & 3) * 2];

#pragma unroll
    for (int mt = 0; mt < 4; mt++) {
#pragma unroll
        for (int half = 0; half < 2; half++) {
            const int row  = wm * 64 + mt * 16 + (lane >> 2) + half * 8;
            const int grow = m0 + row;
            if (grow >= M) continue;
#pragma unroll
            for (int nt = 0; nt < 4; nt++) {
                const int col = wn * 32 + nt * 8 + (lane & 3) * 2;
                float f0 = fmaxf(acc[mt][nt][half * 2 + 0] + bv[nt].x, 0.f);
                float f1 = fmaxf(acc[mt][nt][half * 2 + 1] + bv[nt].y, 0.f);
                uint32_t pk = pack_fp16(__float2half_rn(f0), __float2half_rn(f1));
                if (branch == 0)
                    *(uint32_t*)&g_headH[(size_t)grow * HSZ + col] = pk;
                else
                    *(uint32_t*)&g_tailH[(size_t)grow * HSZ + col] = pk;
            }
        }
    }
}

// ---------------------------------------------------------------------------
// Kernel 2: biaffine v9 — R9's proven m32 x n64 tile / per-r epilogue,
// but 6 r per CTA instead of 24: grid (256, 8) = 2048 CTAs eliminates the
// wave-quantization loss (512 CTAs on 296 slots = 86.5% -> 98.8%).
//   CTA = 128 tokens x 6 r, 256 threads, 8 warps = 4 wm x 2 wn.
// ---------------------------------------------------------------------------
#define AROW 272
#define ATILE (128 * AROW)             // 34816
#define TTILE (128 * AROW)
#define BI_RED (ATILE + TTILE)         // 69632 (2 x 128 floats, double-buffered)
#define BI_SMEM (BI_RED + 1024)        // 70656

__global__ __launch_bounds__(256, 2) void biaffine_mma(
    const int* __restrict__ head_id,
    float* __restrict__ out)
{
    extern __shared__ char sm[];
    const uint32_t sb = smem_u32(sm);
    float* red = (float*)(sm + BI_RED);

    const int t0  = blockIdx.x * 128;
    const int r0  = blockIdx.y * 6;
    const int tid = threadIdx.x;
    const int lane = tid & 31;
    const int warp = tid >> 5;
    const int wm   = warp >> 1;        // 0..3 (32 tokens each)
    const int wn   = warp & 1;         // 0..1 (64 k-cols each)

    // Stage A (gathered head rows) and tail, both fp16, via cp.async.
#pragma unroll
    for (int i = 0; i < 8; i++) {
        int c   = tid + i * 256;
        int row = c >> 4;
        int col = c & 15;
        int t   = t0 + row;
        int hid = head_id[t];
        size_t hbase = ((size_t)(t >> 10) * APP + hid) * HSZ + col * 8;
        CP16(sb + (uint32_t)row * AROW + col * 16, g_headH + hbase);
        CP16(sb + ATILE + (uint32_t)row * AROW + col * 16,
             g_tailH + (size_t)t * HSZ + col * 8);
    }
    CP_COMMIT();
    CP_WAIT0();
    __syncthreads();

    const uint32_t aBase = sb + (uint32_t)(wm * 32 + (lane & 15)) * AROW
                         + (uint32_t)(lane >> 4) * 16;

    // tail smem read base: row = wm*32 + mt*16 + (lane>>2) + half*8
    const char* tbase = sm + ATILE
                      + ((uint32_t)(wm * 32 + (lane >> 2)) * AROW)
                      + (uint32_t)(wn * 64 + (lane & 3) * 2) * 2;

#pragma unroll 1
    for (int rr = 0; rr < 6; rr++) {
        const int r = r0 + rr;
        const uint4* __restrict__ bF = g_Bfrag + (size_t)r * 2048 + wn * 128 + lane;

        float acc[2][8][4];
#pragma unroll
        for (int mt = 0; mt < 2; mt++)
#pragma unroll
            for (int nb = 0; nb < 8; nb++)
#pragma unroll
                for (int e = 0; e < 4; e++) acc[mt][nb][e] = 0.f;

#pragma unroll
        for (int ks = 0; ks < 8; ks++) {
            uint32_t a0[4], a1[4];
            LDMX4(a0, aBase + ks * 32);
            LDMX4(a1, aBase + 16 * AROW + ks * 32);
            const uint4* bk = bF + ks * 256;
#pragma unroll
            for (int gl = 0; gl < 4; gl++) {
                uint4 bv = bk[gl * 32];
                MMA_FP(acc[0][2 * gl],     a0, bv.x, bv.y);
                MMA_FP(acc[0][2 * gl + 1], a0, bv.z, bv.w);
                MMA_FP(acc[1][2 * gl],     a1, bv.x, bv.y);
                MMA_FP(acc[1][2 * gl + 1], a1, bv.z, bv.w);
            }
        }

        // partial k-dot with tail (this warp's 64 cols), quad reduce
        float p[2][2];
#pragma unroll
        for (int mt = 0; mt < 2; mt++) {
#pragma unroll
            for (int half = 0; half < 2; half++) {
                const char* trow = tbase + (uint32_t)(mt * 16 + half * 8) * AROW;
                float s = 0.f;
#pragma unroll
                for (int nb = 0; nb < 8; nb++) {
                    uint32_t tv = *(const uint32_t*)(trow + nb * 16);
                    float2 tf = __half22float2(*(const __half2*)&tv);
                    s += acc[mt][nb][half * 2 + 0] * tf.x
                       + acc[mt][nb][half * 2 + 1] * tf.y;
                }
                s += __shfl_xor_sync(0xffffffffu, s, 1);
                s += __shfl_xor_sync(0xffffffffu, s, 2);
                p[mt][half] = s;
            }
        }

        float* rbuf = red + (rr & 1) * 128;
        if (wn == 0 && (lane & 3) == 0) {
#pragma unroll
            for (int mt = 0; mt < 2; mt++)
#pragma unroll
                for (int half = 0; half < 2; half++) {
                    int lrow = wm * 32 + mt * 16 + (lane >> 2) + half * 8;
                    rbuf[lrow] = p[mt][half];
                }
        }
        __syncthreads();
        if (wn == 1 && (lane & 3) == 0) {
#pragma unroll
            for (int mt = 0; mt < 2; mt++)
#pragma unroll
                for (int half = 0; half < 2; half++) {
                    int lrow = wm * 32 + mt * 16 + (lane >> 2) + half * 8;
                    out[(size_t)(t0 + lrow) * RSZ + r] = rbuf[lrow] + p[mt][half];
                }
        }
    }
}

// ---------------------------------------------------------------------------
extern "C" void kernel_launch(void* const* d_in, const int* in_sizes, int n_in,
                              void* d_out, int out_size)
{
    const float* x       = (const float*)d_in[0];
    const int*   head_id = (const int*)  d_in[1];
    const float* root    = (const float*)d_in[2];
    const float* Wh      = (const float*)d_in[3];
    const float* bh      = (const float*)d_in[4];
    const float* Wt      = (const float*)d_in[5];
    const float* bt      = (const float*)d_in[6];
    const float* Kmat    = (const float*)d_in[7];
    float*       out     = (float*)d_out;

    const int prep_smem = 128 * 129 * sizeof(float);   // 66048
    cudaFuncSetAttribute(prep_k, cudaFuncAttributeMaxDynamicSharedMemorySize, prep_smem);
    prep_k<<<RSZ, 256, prep_smem>>>(Kmat);
    prep_w<<<dim3(24, 2), 256>>>(Wh, Wt);

    cudaFuncSetAttribute(ff_mma, cudaFuncAttributeMaxDynamicSharedMemorySize, FF_SMEM);
    ff_mma<<<dim3(257, 2), 256, FF_SMEM>>>(x, root, bh, bt);

    cudaFuncSetAttribute(biaffine_mma, cudaFuncAttributeMaxDynamicSharedMemorySize, BI_SMEM);
    biaffine_mma<<<dim3(NTOK / 128, RSZ / 6), 256, BI_SMEM>>>(head_id, out);
}

// round 13
// speedup vs baseline: 1.3933x; 1.0179x over previous
#include <cuda_runtime.h>
#include <cuda_bf16.h>
#include <cuda_fp16.h>
#include <cstdint>

// Problem constants
#define BSZ   32
#define SSZ   1024
#define DSZ   768
#define HSZ   128
#define RSZ   48
#define APP   (SSZ + 1)        // 1025
#define NTOK  (BSZ * SSZ)      // 32768
#define MHEAD (BSZ * APP)      // 32800

// Scratch (device globals)
__device__ __half g_headH[(size_t)MHEAD * HSZ];           // fp16 head
__device__ __half g_tailH[(size_t)NTOK * HSZ];            // fp16 tail
__device__ __half g_W16[(size_t)2 * HSZ * DSZ];           // W^T [branch][n][k] fp16
// Fragment-ordered fp16 B image per r: uint4 units: r*2048 + ks*256 + g*32 + lane
__device__ uint4 g_Bfrag[(size_t)RSZ * 2048];

// ---------------------------------------------------------------------------
// PTX helpers (target-suffix-free)
// ---------------------------------------------------------------------------
__device__ __forceinline__ uint32_t smem_u32(const void* p) {
    uint32_t a;
    asm("{ .reg .u64 t; cvta.to.shared.u64 t, %1; cvt.u32.u64 %0, t; }" : "=r"(a) : "l"(p));
    return a;
}

#define CP16(dst, src) \
    asm volatile("cp.async.cg.shared.global [%0], [%1], 16;" :: "r"(dst), "l"(src) : "memory")
#define CP_COMMIT() asm volatile("cp.async.commit_group;" ::: "memory")
#define CP_WAIT0()  asm volatile("cp.async.wait_group 0;" ::: "memory")
#define CP_WAIT1()  asm volatile("cp.async.wait_group 1;" ::: "memory")

#define LDMX4(r, addr) \
    asm volatile("ldmatrix.sync.aligned.m8n8.x4.shared.b16 {%0,%1,%2,%3}, [%4];" \
        : "=r"((r)[0]), "=r"((r)[1]), "=r"((r)[2]), "=r"((r)[3]) : "r"(addr))

#define LDS32(v, addr) \
    asm volatile("ld.shared.b32 %0, [%1];" : "=r"(v) : "r"(addr))
#define LDS128(q, addr) \
    asm volatile("ld.shared.v4.u32 {%0,%1,%2,%3}, [%4];" \
        : "=r"((q).x), "=r"((q).y), "=r"((q).z), "=r"((q).w) : "r"(addr))
#define STS128(addr, q) \
    asm volatile("st.shared.v4.b32 [%0], {%1,%2,%3,%4};" \
        :: "r"(addr), "r"((q).x), "r"((q).y), "r"((q).z), "r"((q).w) : "memory")

// fp16 MMA
#define MMA_FP(c, a, b0, b1) \
    asm volatile("mma.sync.aligned.m16n8k16.row.col.f32.f16.f16.f32 " \
        "{%0,%1,%2,%3}, {%4,%5,%6,%7}, {%8,%9}, {%0,%1,%2,%3};" \
        : "+f"((c)[0]), "+f"((c)[1]), "+f"((c)[2]), "+f"((c)[3]) \
        : "r"((a)[0]), "r"((a)[1]), "r"((a)[2]), "r"((a)[3]), "r"(b0), "r"(b1))

__device__ __forceinline__ uint32_t pack_fp16(__half a, __half b) {
    return (uint32_t)__half_as_ushort(a) | ((uint32_t)__half_as_ushort(b) << 16);
}

// ---------------------------------------------------------------------------
// Kernel 0a: prep K -> fragment-ordered fp16 B images. Widened: grid (48, 4),
// block (r, q) handles ks in {2q, 2q+1}, staging only h rows [32q, 32q+32).
// ---------------------------------------------------------------------------
__global__ __launch_bounds__(256) void prep_k(const float* __restrict__ Kmat)
{
    __shared__ float ksm[32 * 129];
    const int r   = blockIdx.x;
    const int q   = blockIdx.y;              // 0..3
    const int tid = threadIdx.x;
#pragma unroll
    for (int j = 0; j < 16; j++) {
        int idx = tid + j * 256;             // 4096 = 32 rows x 128
        int h = idx >> 7, n = idx & 127;
        ksm[h * 129 + n] = Kmat[(size_t)(q * 32 + h) * (HSZ * RSZ) + r * HSZ + n];
    }
    __syncthreads();

    uint32_t* outH = (uint32_t*)(g_Bfrag + (size_t)r * 2048);
#pragma unroll
    for (int j = 0; j < 8; j++) {
        int v = q * 2048 + tid + j * 256;    // this block's 2048 slots
        int ks   = v >> 10;
        int rem  = v & 1023;
        int g    = rem >> 7;
        int rem2 = rem & 127;
        int lane = rem2 >> 2;
        int hw2  = rem2 & 3;
        int pair = hw2 >> 1, reg = hw2 & 1;
        int n  = (2 * g + pair) * 8 + (lane >> 2);
        int h0 = ks * 16 + reg * 8 + (lane & 3) * 2 - q * 32;   // local row
        float f0 = ksm[h0 * 129 + n];
        float f1 = ksm[(h0 + 1) * 129 + n];
        outH[v] = pack_fp16(__float2half_rn(f0), __float2half_rn(f1));
    }
}

// ---------------------------------------------------------------------------
// Kernel 0b: prep W — transpose Wh/Wt -> fp16 W^T [n][k].
// ---------------------------------------------------------------------------
__global__ __launch_bounds__(256) void prep_w(const float* __restrict__ Wh,
                                              const float* __restrict__ Wt)
{
    __shared__ float tw[32 * 129];
    const int kb = blockIdx.x;
    const int br = blockIdx.y;
    const float* W = br ? Wt : Wh;
    const int tid = threadIdx.x;
#pragma unroll
    for (int j = 0; j < 16; j++) {
        int idx = tid + j * 256;
        int k = idx >> 7;
        int n = idx & 127;
        tw[k * 129 + n] = W[(size_t)(kb * 32 + k) * HSZ + n];
    }
    __syncthreads();
#pragma unroll
    for (int j = 0; j < 16; j++) {
        int idx = tid + j * 256;
        int n = idx >> 5;
        int k = idx & 31;
        g_W16[(size_t)br * HSZ * DSZ + (size_t)n * DSZ + kb * 32 + k] =
            __float2half_rn(tw[k * 129 + n]);
    }
}

// ---------------------------------------------------------------------------
// Kernel 1: dual FF GEMM, fp16 1-pass (proven in R10/R11).
// ---------------------------------------------------------------------------
#define FFROW 80
#define FF_AT (128 * FFROW)                        // 10240
#define FF_BB FF_AT
#define FF_BS FF_AT
#define FF_SMEM (FF_BB + 2 * FF_BS)                // 30720

__global__ __launch_bounds__(256) void ff_mma(
    const float* __restrict__ x,
    const float* __restrict__ root,
    const float* __restrict__ bh, const float* __restrict__ bt)
{
    extern __shared__ char sm[];
    const uint32_t sb = smem_u32(sm);

    const int branch = blockIdx.y;
    const int M      = (branch == 0) ? MHEAD : NTOK;
    const int m0     = blockIdx.x * 128;
    if (m0 >= M) return;

    const float* bias = (branch == 0) ? bh : bt;
    const __half* WB  = g_W16 + (size_t)branch * HSZ * DSZ;

    const int tid  = threadIdx.x;
    const int lane = tid & 31;
    const int warp = tid >> 5;
    const int wm   = warp >> 2;
    const int wn   = warp & 3;

    const float* arow[4];
    bool rowok[4];
    int rown[4], colf[4];
#pragma unroll
    for (int i = 0; i < 4; i++) {
        int c   = tid + i * 256;
        int row = c >> 3;
        int c4  = c & 7;
        rown[i] = row; colf[i] = c4;
        int g = m0 + row;
        const float* p = nullptr;
        bool ok = (g < M);
        if (ok) {
            if (branch == 0) {
                int b  = g / APP;
                int ii = g - b * APP;
                p = (ii == 0) ? root : (x + (size_t)(b * SSZ + (ii - 1)) * DSZ);
            } else {
                p = x + (size_t)g * DSZ;
            }
        }
        arow[i] = p; rowok[i] = ok;
    }

    auto load_B = [&](uint32_t buf, int k0) {
#pragma unroll
        for (int i = 0; i < 2; i++) {
            int c   = tid + i * 256;
            int row = c >> 2;
            int c4  = c & 3;
            CP16(buf + row * FFROW + c4 * 16, WB + (size_t)row * DSZ + k0 + c4 * 8);
        }
    };

    float4 va[4];
#pragma unroll
    for (int i = 0; i < 4; i++)
        va[i] = rowok[i] ? *(const float4*)(arow[i] + colf[i] * 4)
                         : make_float4(0.f, 0.f, 0.f, 0.f);
    load_B(sb + FF_BB, 0);
    CP_COMMIT();

    float acc[4][4][4];
#pragma unroll
    for (int mt = 0; mt < 4; mt++)
#pragma unroll
        for (int nt = 0; nt < 4; nt++)
#pragma unroll
            for (int e = 0; e < 4; e++) acc[mt][nt][e] = 0.f;

    const uint32_t aLaneOff = (uint32_t)(wm * 64 + (lane & 15)) * FFROW
                            + (uint32_t)(lane >> 4) * 16;
    const uint32_t bLaneOff = (uint32_t)(wn * 32 + (lane & 7) + ((lane >> 4) << 3)) * FFROW
                            + (uint32_t)((lane >> 3) & 1) * 16;

#pragma unroll 1
    for (int ch = 0; ch < 24; ch++) {
        const int nxt = ch + 1;
        if (nxt < 24) load_B(sb + FF_BB + (nxt & 1) * FF_BS, nxt * 32);
        CP_COMMIT();

#pragma unroll
        for (int i = 0; i < 4; i++) {
            uint32_t w0 = pack_fp16(__float2half_rn(va[i].x), __float2half_rn(va[i].y));
            uint32_t w1 = pack_fp16(__float2half_rn(va[i].z), __float2half_rn(va[i].w));
            *(uint2*)(sm + rown[i] * FFROW + colf[i] * 8) = make_uint2(w0, w1);
        }
        if (nxt < 24) {
#pragma unroll
            for (int i = 0; i < 4; i++)
                va[i] = rowok[i] ? *(const float4*)(arow[i] + nxt * 32 + colf[i] * 4)
                                 : make_float4(0.f, 0.f, 0.f, 0.f);
        }
        CP_WAIT1();
        __syncthreads();

        const uint32_t aB = sb + aLaneOff;
        const uint32_t bB = sb + FF_BB + (ch & 1) * FF_BS + bLaneOff;
#pragma unroll
        for (int ks = 0; ks < 2; ks++) {
            uint32_t aF[4][4];
#pragma unroll
            for (int mt = 0; mt < 4; mt++)
                LDMX4(aF[mt], aB + (uint32_t)mt * 16 * FFROW + (uint32_t)ks * 32);
            uint32_t bF[2][4];
#pragma unroll
            for (int np = 0; np < 2; np++)
                LDMX4(bF[np], bB + (uint32_t)np * 16 * FFROW + (uint32_t)ks * 32);
#pragma unroll
            for (int mt = 0; mt < 4; mt++)
#pragma unroll
                for (int nt = 0; nt < 4; nt++)
                    MMA_FP(acc[mt][nt], aF[mt],
                           bF[nt >> 1][(nt & 1) * 2], bF[nt >> 1][(nt & 1) * 2 + 1]);
        }
        __syncthreads();
    }

    float2 bv[4];
#pragma unroll
    for (int nt = 0; nt < 4; nt++)
        bv[nt] = *(const float2*)&bias[wn * 32 + nt * 8 + (lane & 3) * 2];

#pragma unroll
    for (int mt = 0; mt < 4; mt++) {
#pragma unroll
        for (int half = 0; half < 2; half++) {
            const int row  = wm * 64 + mt * 16 + (lane >> 2) + half * 8;
            const int grow = m0 + row;
            if (grow >= M) continue;
#pragma unroll
            for (int nt = 0; nt < 4; nt++) {
                const int col = wn * 32 + nt * 8 + (lane & 3) * 2;
                float f0 = fmaxf(acc[mt][nt][half * 2 + 0] + bv[nt].x, 0.f);
                float f1 = fmaxf(acc[mt][nt][half * 2 + 1] + bv[nt].y, 0.f);
                uint32_t pk = pack_fp16(__float2half_rn(f0), __float2half_rn(f1));
                if (branch == 0)
                    *(uint32_t*)&g_headH[(size_t)grow * HSZ + col] = pk;
                else
                    *(uint32_t*)&g_tailH[(size_t)grow * HSZ + col] = pk;
            }
        }
    }
}

// ---------------------------------------------------------------------------
// Kernel 2: biaffine v10 — v9 (m32 x n64, 128 tok x 6 r, 2 CTA/SM) plus a
// one-time tail PERMUTE: after staging, each thread gathers its 32 epilogue
// tail values (32 LDS.32, once per CTA), barrier, re-stores them packed
// fragment-major OVERLAYED on the dead tail tile. Epilogue per r then uses
// 8 LDS.128 per thread instead of 32 scattered LDS.32.
//   perm layout: off = warp*4096 + combo*1024 + lane*32 (+16), combo = mt*2+half.
// ---------------------------------------------------------------------------
#define AROW 272
#define ATILE (128 * AROW)             // 34816
#define TTILE (128 * AROW)
#define BI_RED (ATILE + TTILE)         // 69632 (2 x 128 floats, double-buffered)
#define BI_SMEM (BI_RED + 1024)        // 70656
#define PERM_OFF ATILE                 // permuted tail overlays the tail tile

__global__ __launch_bounds__(256, 2) void biaffine_mma(
    const int* __restrict__ head_id,
    float* __restrict__ out)
{
    extern __shared__ char sm[];
    const uint32_t sb = smem_u32(sm);
    float* red = (float*)(sm + BI_RED);

    const int t0  = blockIdx.x * 128;
    const int r0  = blockIdx.y * 6;
    const int tid = threadIdx.x;
    const int lane = tid & 31;
    const int warp = tid >> 5;
    const int wm   = warp >> 1;        // 0..3 (32 tokens each)
    const int wn   = warp & 1;         // 0..1 (64 k-cols each)

    // Stage A (gathered head rows) and tail, both fp16, via cp.async.
#pragma unroll
    for (int i = 0; i < 8; i++) {
        int c   = tid + i * 256;
        int row = c >> 4;
        int col = c & 15;
        int t   = t0 + row;
        int hid = head_id[t];
        size_t hbase = ((size_t)(t >> 10) * APP + hid) * HSZ + col * 8;
        CP16(sb + (uint32_t)row * AROW + col * 16, g_headH + hbase);
        CP16(sb + ATILE + (uint32_t)row * AROW + col * 16,
             g_tailH + (size_t)t * HSZ + col * 8);
    }
    CP_COMMIT();
    CP_WAIT0();
    __syncthreads();

    // ---- tail permute: gather this thread's 32 epilogue values, pack ----
    uint32_t tv[4][8];
#pragma unroll
    for (int combo = 0; combo < 4; combo++) {
        const int mt = combo >> 1, half = combo & 1;
        const int row = wm * 32 + mt * 16 + (lane >> 2) + half * 8;
        const uint32_t rbase = sb + ATILE + (uint32_t)row * AROW
                             + (uint32_t)(wn * 64 + (lane & 3) * 2) * 2;
#pragma unroll
        for (int nb = 0; nb < 8; nb++)
            LDS32(tv[combo][nb], rbase + nb * 16);
    }
    __syncthreads();            // all reads done before overlay writes
    {
        const uint32_t pbase = sb + PERM_OFF + (uint32_t)warp * 4096
                             + (uint32_t)lane * 32;
#pragma unroll
        for (int combo = 0; combo < 4; combo++) {
            uint4 q0 = make_uint4(tv[combo][0], tv[combo][1], tv[combo][2], tv[combo][3]);
            uint4 q1 = make_uint4(tv[combo][4], tv[combo][5], tv[combo][6], tv[combo][7]);
            STS128(pbase + combo * 1024,      q0);
            STS128(pbase + combo * 1024 + 16, q1);
        }
    }
    __syncthreads();

    const uint32_t aBase = sb + (uint32_t)(wm * 32 + (lane & 15)) * AROW
                         + (uint32_t)(lane >> 4) * 16;
    const uint32_t permBase = sb + PERM_OFF + (uint32_t)warp * 4096
                            + (uint32_t)lane * 32;

#pragma unroll 1
    for (int rr = 0; rr < 6; rr++) {
        const int r = r0 + rr;
        const uint4* __restrict__ bF = g_Bfrag + (size_t)r * 2048 + wn * 128 + lane;

        float acc[2][8][4];
#pragma unroll
        for (int mt = 0; mt < 2; mt++)
#pragma unroll
            for (int nb = 0; nb < 8; nb++)
#pragma unroll
                for (int e = 0; e < 4; e++) acc[mt][nb][e] = 0.f;

#pragma unroll
        for (int ks = 0; ks < 8; ks++) {
            uint32_t a0[4], a1[4];
            LDMX4(a0, aBase + ks * 32);
            LDMX4(a1, aBase + 16 * AROW + ks * 32);
            const uint4* bk = bF + ks * 256;
#pragma unroll
            for (int gl = 0; gl < 4; gl++) {
                uint4 bv = bk[gl * 32];
                MMA_FP(acc[0][2 * gl],     a0, bv.x, bv.y);
                MMA_FP(acc[0][2 * gl + 1], a0, bv.z, bv.w);
                MMA_FP(acc[1][2 * gl],     a1, bv.x, bv.y);
                MMA_FP(acc[1][2 * gl + 1], a1, bv.z, bv.w);
            }
        }

        // epilogue: packed tail loads (2 x LDS.128 per combo), quad reduce
        float p[2][2];
#pragma unroll
        for (int mt = 0; mt < 2; mt++) {
#pragma unroll
            for (int half = 0; half < 2; half++) {
                const uint32_t addr = permBase + (uint32_t)(mt * 2 + half) * 1024;
                uint4 q0, q1;
                LDS128(q0, addr);
                LDS128(q1, addr + 16);
                uint32_t w[8] = {q0.x, q0.y, q0.z, q0.w, q1.x, q1.y, q1.z, q1.w};
                float s = 0.f;
#pragma unroll
                for (int nb = 0; nb < 8; nb++) {
                    float2 tf = __half22float2(*(const __half2*)&w[nb]);
                    s += acc[mt][nb][half * 2 + 0] * tf.x
                       + acc[mt][nb][half * 2 + 1] * tf.y;
                }
                s += __shfl_xor_sync(0xffffffffu, s, 1);
                s += __shfl_xor_sync(0xffffffffu, s, 2);
                p[mt][half] = s;
            }
        }

        float* rbuf = red + (rr & 1) * 128;
        if (wn == 0 && (lane & 3) == 0) {
#pragma unroll
            for (int mt = 0; mt < 2; mt++)
#pragma unroll
                for (int half = 0; half < 2; half++) {
                    int lrow = wm * 32 + mt * 16 + (lane >> 2) + half * 8;
                    rbuf[lrow] = p[mt][half];
                }
        }
        __syncthreads();
        if (wn == 1 && (lane & 3) == 0) {
#pragma unroll
            for (int mt = 0; mt < 2; mt++)
#pragma unroll
                for (int half = 0; half < 2; half++) {
                    int lrow = wm * 32 + mt * 16 + (lane >> 2) + half * 8;
                    out[(size_t)(t0 + lrow) * RSZ + r] = rbuf[lrow] + p[mt][half];
                }
        }
    }
}

// ---------------------------------------------------------------------------
extern "C" void kernel_launch(void* const* d_in, const int* in_sizes, int n_in,
                              void* d_out, int out_size)
{
    const float* x       = (const float*)d_in[0];
    const int*   head_id = (const int*)  d_in[1];
    const float* root    = (const float*)d_in[2];
    const float* Wh      = (const float*)d_in[3];
    const float* bh      = (const float*)d_in[4];
    const float* Wt      = (const float*)d_in[5];
    const float* bt      = (const float*)d_in[6];
    const float* Kmat    = (const float*)d_in[7];
    float*       out     = (float*)d_out;

    prep_k<<<dim3(RSZ, 4), 256>>>(Kmat);
    prep_w<<<dim3(24, 2), 256>>>(Wh, Wt);

    cudaFuncSetAttribute(ff_mma, cudaFuncAttributeMaxDynamicSharedMemorySize, FF_SMEM);
    ff_mma<<<dim3(257, 2), 256, FF_SMEM>>>(x, root, bh, bt);

    cudaFuncSetAttribute(biaffine_mma, cudaFuncAttributeMaxDynamicSharedMemorySize, BI_SMEM);
    biaffine_mma<<<dim3(NTOK / 128, RSZ / 6), 256, BI_SMEM>>>(head_id, out);
}

// round 14
// speedup vs baseline: 1.4485x; 1.0396x over previous
#include <cuda_runtime.h>
#include <cuda_bf16.h>
#include <cuda_fp16.h>
#include <cstdint>

// Problem constants
#define BSZ   32
#define SSZ   1024
#define DSZ   768
#define HSZ   128
#define RSZ   48
#define APP   (SSZ + 1)        // 1025
#define NTOK  (BSZ * SSZ)      // 32768
#define MHEAD (BSZ * APP)      // 32800

// Scratch (device globals)
__device__ __half g_headH[(size_t)MHEAD * HSZ];           // fp16 head
__device__ __half g_tailH[(size_t)NTOK * HSZ];            // fp16 tail
__device__ __half g_W16[(size_t)2 * HSZ * DSZ];           // W^T [branch][n][k] fp16
// Fragment-ordered fp16 B image per r: uint4 units: r*2048 + ks*256 + g*32 + lane
__device__ uint4 g_Bfrag[(size_t)RSZ * 2048];

// ---------------------------------------------------------------------------
// PTX helpers (target-suffix-free)
// ---------------------------------------------------------------------------
__device__ __forceinline__ uint32_t smem_u32(const void* p) {
    uint32_t a;
    asm("{ .reg .u64 t; cvta.to.shared.u64 t, %1; cvt.u32.u64 %0, t; }" : "=r"(a) : "l"(p));
    return a;
}

#define CP16(dst, src) \
    asm volatile("cp.async.cg.shared.global [%0], [%1], 16;" :: "r"(dst), "l"(src) : "memory")
#define CP_COMMIT() asm volatile("cp.async.commit_group;" ::: "memory")
#define CP_WAIT0()  asm volatile("cp.async.wait_group 0;" ::: "memory")
#define CP_WAIT1()  asm volatile("cp.async.wait_group 1;" ::: "memory")

#define LDMX4(r, addr) \
    asm volatile("ldmatrix.sync.aligned.m8n8.x4.shared.b16 {%0,%1,%2,%3}, [%4];" \
        : "=r"((r)[0]), "=r"((r)[1]), "=r"((r)[2]), "=r"((r)[3]) : "r"(addr))

// fp16 MMA
#define MMA_FP(c, a, b0, b1) \
    asm volatile("mma.sync.aligned.m16n8k16.row.col.f32.f16.f16.f32 " \
        "{%0,%1,%2,%3}, {%4,%5,%6,%7}, {%8,%9}, {%0,%1,%2,%3};" \
        : "+f"((c)[0]), "+f"((c)[1]), "+f"((c)[2]), "+f"((c)[3]) \
        : "r"((a)[0]), "r"((a)[1]), "r"((a)[2]), "r"((a)[3]), "r"(b0), "r"(b1))

__device__ __forceinline__ uint32_t pack_fp16(__half a, __half b) {
    return (uint32_t)__half_as_ushort(a) | ((uint32_t)__half_as_ushort(b) << 16);
}

// ---------------------------------------------------------------------------
// Kernel 0: fused prep. grid (48, 5).
//   y in [0,4): prep_k quadrant q=y for r=x (fragment-ordered fp16 B image).
//   y == 4   : prep_w for x<48 (kb = x%24, br = x/24).
// ---------------------------------------------------------------------------
__global__ __launch_bounds__(256) void prep_all(const float* __restrict__ Kmat,
                                                const float* __restrict__ Wh,
                                                const float* __restrict__ Wt)
{
    __shared__ float stage[32 * 129];
    const int tid = threadIdx.x;

    if (blockIdx.y < 4) {
        // ---- prep_k quadrant ----
        const int r = blockIdx.x;
        const int q = blockIdx.y;            // 0..3
#pragma unroll
        for (int j = 0; j < 16; j++) {
            int idx = tid + j * 256;         // 4096 = 32 rows x 128
            int h = idx >> 7, n = idx & 127;
            stage[h * 129 + n] = Kmat[(size_t)(q * 32 + h) * (HSZ * RSZ) + r * HSZ + n];
        }
        __syncthreads();

        uint32_t* outH = (uint32_t*)(g_Bfrag + (size_t)r * 2048);
#pragma unroll
        for (int j = 0; j < 8; j++) {
            int v = q * 2048 + tid + j * 256;
            int ks   = v >> 10;
            int rem  = v & 1023;
            int g    = rem >> 7;
            int rem2 = rem & 127;
            int lane = rem2 >> 2;
            int hw2  = rem2 & 3;
            int pair = hw2 >> 1, reg = hw2 & 1;
            int n  = (2 * g + pair) * 8 + (lane >> 2);
            int h0 = ks * 16 + reg * 8 + (lane & 3) * 2 - q * 32;   // local row
            float f0 = stage[h0 * 129 + n];
            float f1 = stage[(h0 + 1) * 129 + n];
            outH[v] = pack_fp16(__float2half_rn(f0), __float2half_rn(f1));
        }
    } else {
        // ---- prep_w ----
        if (blockIdx.x >= 48) return;
        const int kb = blockIdx.x % 24;
        const int br = blockIdx.x / 24;
        const float* W = br ? Wt : Wh;
#pragma unroll
        for (int j = 0; j < 16; j++) {
            int idx = tid + j * 256;
            int k = idx >> 7;
            int n = idx & 127;
            stage[k * 129 + n] = W[(size_t)(kb * 32 + k) * HSZ + n];
        }
        __syncthreads();
#pragma unroll
        for (int j = 0; j < 16; j++) {
            int idx = tid + j * 256;
            int n = idx >> 5;
            int k = idx & 31;
            g_W16[(size_t)br * HSZ * DSZ + (size_t)n * DSZ + kb * 32 + k] =
                __float2half_rn(stage[k * 129 + n]);
        }
    }
}

// ---------------------------------------------------------------------------
// Kernel 1: dual FF GEMM, fp16 1-pass (proven in R10-R13).
// ---------------------------------------------------------------------------
#define FFROW 80
#define FF_AT (128 * FFROW)                        // 10240
#define FF_BB FF_AT
#define FF_BS FF_AT
#define FF_SMEM (FF_BB + 2 * FF_BS)                // 30720

__global__ __launch_bounds__(256) void ff_mma(
    const float* __restrict__ x,
    const float* __restrict__ root,
    const float* __restrict__ bh, const float* __restrict__ bt)
{
    extern __shared__ char sm[];
    const uint32_t sb = smem_u32(sm);

    const int branch = blockIdx.y;
    const int M      = (branch == 0) ? MHEAD : NTOK;
    const int m0     = blockIdx.x * 128;
    if (m0 >= M) return;

    const float* bias = (branch == 0) ? bh : bt;
    const __half* WB  = g_W16 + (size_t)branch * HSZ * DSZ;

    const int tid  = threadIdx.x;
    const int lane = tid & 31;
    const int warp = tid >> 5;
    const int wm   = warp >> 2;
    const int wn   = warp & 3;

    const float* arow[4];
    bool rowok[4];
    int rown[4], colf[4];
#pragma unroll
    for (int i = 0; i < 4; i++) {
        int c   = tid + i * 256;
        int row = c >> 3;
        int c4  = c & 7;
        rown[i] = row; colf[i] = c4;
        int g = m0 + row;
        const float* p = nullptr;
        bool ok = (g < M);
        if (ok) {
            if (branch == 0) {
                int b  = g / APP;
                int ii = g - b * APP;
                p = (ii == 0) ? root : (x + (size_t)(b * SSZ + (ii - 1)) * DSZ);
            } else {
                p = x + (size_t)g * DSZ;
            }
        }
        arow[i] = p; rowok[i] = ok;
    }

    auto load_B = [&](uint32_t buf, int k0) {
#pragma unroll
        for (int i = 0; i < 2; i++) {
            int c   = tid + i * 256;
            int row = c >> 2;
            int c4  = c & 3;
            CP16(buf + row * FFROW + c4 * 16, WB + (size_t)row * DSZ + k0 + c4 * 8);
        }
    };

    float4 va[4];
#pragma unroll
    for (int i = 0; i < 4; i++)
        va[i] = rowok[i] ? *(const float4*)(arow[i] + colf[i] * 4)
                         : make_float4(0.f, 0.f, 0.f, 0.f);
    load_B(sb + FF_BB, 0);
    CP_COMMIT();

    float acc[4][4][4];
#pragma unroll
    for (int mt = 0; mt < 4; mt++)
#pragma unroll
        for (int nt = 0; nt < 4; nt++)
#pragma unroll
            for (int e = 0; e < 4; e++) acc[mt][nt][e] = 0.f;

    const uint32_t aLaneOff = (uint32_t)(wm * 64 + (lane & 15)) * FFROW
                            + (uint32_t)(lane >> 4) * 16;
    const uint32_t bLaneOff = (uint32_t)(wn * 32 + (lane & 7) + ((lane >> 4) << 3)) * FFROW
                            + (uint32_t)((lane >> 3) & 1) * 16;

#pragma unroll 1
    for (int ch = 0; ch < 24; ch++) {
        const int nxt = ch + 1;
        if (nxt < 24) load_B(sb + FF_BB + (nxt & 1) * FF_BS, nxt * 32);
        CP_COMMIT();

#pragma unroll
        for (int i = 0; i < 4; i++) {
            uint32_t w0 = pack_fp16(__float2half_rn(va[i].x), __float2half_rn(va[i].y));
            uint32_t w1 = pack_fp16(__float2half_rn(va[i].z), __float2half_rn(va[i].w));
            *(uint2*)(sm + rown[i] * FFROW + colf[i] * 8) = make_uint2(w0, w1);
        }
        if (nxt < 24) {
#pragma unroll
            for (int i = 0; i < 4; i++)
                va[i] = rowok[i] ? *(const float4*)(arow[i] + nxt * 32 + colf[i] * 4)
                                 : make_float4(0.f, 0.f, 0.f, 0.f);
        }
        CP_WAIT1();
        __syncthreads();

        const uint32_t aB = sb + aLaneOff;
        const uint32_t bB = sb + FF_BB + (ch & 1) * FF_BS + bLaneOff;
#pragma unroll
        for (int ks = 0; ks < 2; ks++) {
            uint32_t aF[4][4];
#pragma unroll
            for (int mt = 0; mt < 4; mt++)
                LDMX4(aF[mt], aB + (uint32_t)mt * 16 * FFROW + (uint32_t)ks * 32);
            uint32_t bF[2][4];
#pragma unroll
            for (int np = 0; np < 2; np++)
                LDMX4(bF[np], bB + (uint32_t)np * 16 * FFROW + (uint32_t)ks * 32);
#pragma unroll
            for (int mt = 0; mt < 4; mt++)
#pragma unroll
                for (int nt = 0; nt < 4; nt++)
                    MMA_FP(acc[mt][nt], aF[mt],
                           bF[nt >> 1][(nt & 1) * 2], bF[nt >> 1][(nt & 1) * 2 + 1]);
        }
        __syncthreads();
    }

    float2 bv[4];
#pragma unroll
    for (int nt = 0; nt < 4; nt++)
        bv[nt] = *(const float2*)&bias[wn * 32 + nt * 8 + (lane & 3) * 2];

#pragma unroll
    for (int mt = 0; mt < 4; mt++) {
#pragma unroll
        for (int half = 0; half < 2; half++) {
            const int row  = wm * 64 + mt * 16 + (lane >> 2) + half * 8;
            const int grow = m0 + row;
            if (grow >= M) continue;
#pragma unroll
            for (int nt = 0; nt < 4; nt++) {
                const int col = wn * 32 + nt * 8 + (lane & 3) * 2;
                float f0 = fmaxf(acc[mt][nt][half * 2 + 0] + bv[nt].x, 0.f);
                float f1 = fmaxf(acc[mt][nt][half * 2 + 1] + bv[nt].y, 0.f);
                uint32_t pk = pack_fp16(__float2half_rn(f0), __float2half_rn(f1));
                if (branch == 0)
                    *(uint32_t*)&g_headH[(size_t)grow * HSZ + col] = pk;
                else
                    *(uint32_t*)&g_tailH[(size_t)grow * HSZ + col] = pk;
            }
        }
    }
}

// ---------------------------------------------------------------------------
// Kernel 2: biaffine v11 — R12's proven m32 x n64 / 128 tok x 6 r core
// (NO permute), with deferred output: per-r partials go to redA/redB slots,
// ONE end barrier, then a coalesced combined store pass.
// ---------------------------------------------------------------------------
#define AROW 272
#define ATILE (128 * AROW)             // 34816
#define TTILE (128 * AROW)
#define BI_REDA (ATILE + TTILE)        // 69632
#define BI_REDB (BI_REDA + 6 * 128 * 4)    // +3072
#define BI_SMEM (BI_REDB + 6 * 128 * 4)    // 75776

__global__ __launch_bounds__(256, 2) void biaffine_mma(
    const int* __restrict__ head_id,
    float* __restrict__ out)
{
    extern __shared__ char sm[];
    const uint32_t sb = smem_u32(sm);
    float* redA = (float*)(sm + BI_REDA);
    float* redB = (float*)(sm + BI_REDB);

    const int t0  = blockIdx.x * 128;
    const int r0  = blockIdx.y * 6;
    const int tid = threadIdx.x;
    const int lane = tid & 31;
    const int warp = tid >> 5;
    const int wm   = warp >> 1;        // 0..3 (32 tokens each)
    const int wn   = warp & 1;         // 0..1 (64 k-cols each)

    // Stage A (gathered head rows) and tail, both fp16, via cp.async.
#pragma unroll
    for (int i = 0; i < 8; i++) {
        int c   = tid + i * 256;
        int row = c >> 4;
        int col = c & 15;
        int t   = t0 + row;
        int hid = head_id[t];
        size_t hbase = ((size_t)(t >> 10) * APP + hid) * HSZ + col * 8;
        CP16(sb + (uint32_t)row * AROW + col * 16, g_headH + hbase);
        CP16(sb + ATILE + (uint32_t)row * AROW + col * 16,
             g_tailH + (size_t)t * HSZ + col * 8);
    }
    CP_COMMIT();
    CP_WAIT0();
    __syncthreads();

    const uint32_t aBase = sb + (uint32_t)(wm * 32 + (lane & 15)) * AROW
                         + (uint32_t)(lane >> 4) * 16;

    // tail smem read base: row = wm*32 + mt*16 + (lane>>2) + half*8
    const char* tbase = sm + ATILE
                      + ((uint32_t)(wm * 32 + (lane >> 2)) * AROW)
                      + (uint32_t)(wn * 64 + (lane & 3) * 2) * 2;

    float* rbuf = (wn == 0) ? redA : redB;

#pragma unroll 1
    for (int rr = 0; rr < 6; rr++) {
        const int r = r0 + rr;
        const uint4* __restrict__ bF = g_Bfrag + (size_t)r * 2048 + wn * 128 + lane;

        float acc[2][8][4];
#pragma unroll
        for (int mt = 0; mt < 2; mt++)
#pragma unroll
            for (int nb = 0; nb < 8; nb++)
#pragma unroll
                for (int e = 0; e < 4; e++) acc[mt][nb][e] = 0.f;

#pragma unroll
        for (int ks = 0; ks < 8; ks++) {
            uint32_t a0[4], a1[4];
            LDMX4(a0, aBase + ks * 32);
            LDMX4(a1, aBase + 16 * AROW + ks * 32);
            const uint4* bk = bF + ks * 256;
#pragma unroll
            for (int gl = 0; gl < 4; gl++) {
                uint4 bv = bk[gl * 32];
                MMA_FP(acc[0][2 * gl],     a0, bv.x, bv.y);
                MMA_FP(acc[0][2 * gl + 1], a0, bv.z, bv.w);
                MMA_FP(acc[1][2 * gl],     a1, bv.x, bv.y);
                MMA_FP(acc[1][2 * gl + 1], a1, bv.z, bv.w);
            }
        }

        // partial k-dot with tail (this warp's 64 cols), quad reduce,
        // write to this r's slot (no barrier).
#pragma unroll
        for (int mt = 0; mt < 2; mt++) {
#pragma unroll
            for (int half = 0; half < 2; half++) {
                const char* trow = tbase + (uint32_t)(mt * 16 + half * 8) * AROW;
                float s = 0.f;
#pragma unroll
                for (int nb = 0; nb < 8; nb++) {
                    uint32_t tv = *(const uint32_t*)(trow + nb * 16);
                    float2 tf = __half22float2(*(const __half2*)&tv);
                    s += acc[mt][nb][half * 2 + 0] * tf.x
                       + acc[mt][nb][half * 2 + 1] * tf.y;
                }
                s += __shfl_xor_sync(0xffffffffu, s, 1);
                s += __shfl_xor_sync(0xffffffffu, s, 2);
                if ((lane & 3) == 0) {
                    int lrow = wm * 32 + mt * 16 + (lane >> 2) + half * 8;
                    rbuf[rr * 128 + lrow] = s;
                }
            }
        }
    }

    // single barrier, then coalesced combined store (24B runs per token)
    __syncthreads();
#pragma unroll
    for (int i = 0; i < 3; i++) {
        int idx  = tid + i * 256;          // 0..767
        int lrow = idx / 6;
        int rr   = idx - lrow * 6;
        out[(size_t)(t0 + lrow) * RSZ + (r0 + rr)] =
            redA[rr * 128 + lrow] + redB[rr * 128 + lrow];
    }
}

// ---------------------------------------------------------------------------
extern "C" void kernel_launch(void* const* d_in, const int* in_sizes, int n_in,
                              void* d_out, int out_size)
{
    const float* x       = (const float*)d_in[0];
    const int*   head_id = (const int*)  d_in[1];
    const float* root    = (const float*)d_in[2];
    const float* Wh      = (const float*)d_in[3];
    const float* bh      = (const float*)d_in[4];
    const float* Wt      = (const float*)d_in[5];
    const float* bt      = (const float*)d_in[6];
    const float* Kmat    = (const float*)d_in[7];
    float*       out     = (float*)d_out;

    prep_all<<<dim3(RSZ, 5), 256>>>(Kmat, Wh, Wt);

    cudaFuncSetAttribute(ff_mma, cudaFuncAttributeMaxDynamicSharedMemorySize, FF_SMEM);
    ff_mma<<<dim3(257, 2), 256, FF_SMEM>>>(x, root, bh, bt);

    cudaFuncSetAttribute(biaffine_mma, cudaFuncAttributeMaxDynamicSharedMemorySize, BI_SMEM);
    biaffine_mma<<<dim3(NTOK / 128, RSZ / 6), 256, BI_SMEM>>>(head_id, out);
}